// round 10
// baseline (speedup 1.0000x reference)
#include <cuda_runtime.h>
#include <cuda_fp16.h>
#include <cstdint>

#define NN 100000
#define NE 1600000
#define FDIM 128
#define NCLS 40

// ------------------------- device scratch (no allocs) -----------------------
__device__ __align__(16) __half g_mh[(size_t)NN * FDIM];   // pool messages (fp16)
__device__ __align__(16) __half g_aggh[(size_t)NN * FDIM]; // segment-max agg (fp16)
__device__ __align__(16) __half g_hh[(size_t)NN * FDIM];   // layer-1 hidden (fp16)
__device__ __align__(16) __half g_xh[(size_t)NN * FDIM];   // fp16 in_feat
__device__ __align__(16) __half g_wh[75776];               // fp16 weights (6 matrices)
__device__ int   g_deg[NN];
__device__ int   g_off[NN + 1];
__device__ int   g_pos[NN];
__device__ int   g_csr[NE];
__device__ int   g_part[128];               // scan tile partials

// weight offsets inside g_wh
#define WR_PW1 0
#define WR_SW1 16384
#define WR_NW1 32768
#define WR_PW2 49152
#define WR_SW2 65536
#define WR_NW2 70656

// ------------------------- PTX helpers --------------------------------------
__device__ __forceinline__ uint32_t smem_to_u32(const void* p) {
    uint32_t a;
    asm("{ .reg .u64 t; cvta.to.shared.u64 t, %1; cvt.u32.u64 %0, t; }"
        : "=r"(a) : "l"(p));
    return a;
}
#define CPASYNC16(sa, ga, sz) \
    asm volatile("cp.async.cg.shared.global [%0], [%1], 16, %2;" \
                 :: "r"(sa), "l"(ga), "r"(sz))
#define CPCOMMIT() asm volatile("cp.async.commit_group;" ::: "memory")
#define CPWAIT(N)  asm volatile("cp.async.wait_group %0;" :: "n"(N) : "memory")

// m16n8k16 fp16 HMMA, f32 accum. Base PTX (sm_80+): compiles at compute_103.
__device__ __forceinline__ void mma_f16(float* d, const uint32_t* a, const uint32_t* b)
{
    asm volatile(
        "mma.sync.aligned.m16n8k16.row.col.f32.f16.f16.f32 "
        "{%0,%1,%2,%3}, {%4,%5,%6,%7}, {%8,%9}, {%0,%1,%2,%3};"
        : "+f"(d[0]), "+f"(d[1]), "+f"(d[2]), "+f"(d[3])
        : "r"(a[0]), "r"(a[1]), "r"(a[2]), "r"(a[3]),
          "r"(b[0]), "r"(b[1]));
}

#define KP 72   // padded smem k stride (halves)

// ------------------------- fp16 warp-MMA GEMM (generic) ----------------------
template<int BN, bool DUAL, bool OUT_HALF>
__global__ void __launch_bounds__(256, 2) mma_gemm_kernel(
    const __half* __restrict__ X0, const __half* __restrict__ X1,
    const __half* __restrict__ W0, const __half* __restrict__ W1,
    const float* __restrict__ b0, const float* __restrict__ b1,
    void* __restrict__ out_v, int n, int fout, int do_relu)
{
    constexpr int NF = BN / 16;
    extern __shared__ __align__(16) __half smem_h[];
    __half* As = smem_h;                     // [2][128*KP]
    __half* Bs = smem_h + 2 * 128 * KP;      // [2][BN*KP]
    float* bias_s = (float*)(smem_h + 2 * 128 * KP + 2 * BN * KP);

    const int tid   = threadIdx.x;
    const int lane  = tid & 31, wid = tid >> 5;
    const int g     = lane >> 2, tig = lane & 3;
    const int m_base = (wid & 3) * 32;
    const int n_base = (wid >> 2) * (BN / 2);
    const int row0  = blockIdx.x * 128;
    const uint32_t sbA = smem_to_u32(smem_h);
    const uint32_t sbB = sbA + 2 * 128 * KP * 2;

    if (tid < BN) {
        float bv = 0.f;
        if (tid < fout) { bv = b0[tid]; if (b1 != nullptr) bv += b1[tid]; }
        bias_s[tid] = bv;
    }

    auto load_chunk = [&](int c, int buf) {
        const __half* X = (c < 2) ? X0 : X1;
        const __half* W = (c < 2) ? W0 : W1;
        const int kc = (c & 1) * 64;
        #pragma unroll
        for (int i = 0; i < 4; i++) {
            int lin = i * 256 + tid;
            int r = lin >> 3, s = lin & 7;
            int gr = row0 + r;
            int ok = (gr < n);
            const __half* src = X + (size_t)(ok ? gr : 0) * 128 + kc + s * 8;
            uint32_t sa = sbA + (uint32_t)(buf * 128 * KP + r * KP + s * 8) * 2;
            CPASYNC16(sa, src, ok ? 16 : 0);
        }
        #pragma unroll
        for (int i = 0; i < (BN * 8 + 255) / 256; i++) {
            int lin = i * 256 + tid;
            if (lin < BN * 8) {
                int r = lin >> 3, s = lin & 7;
                int ok = (r < fout);
                const __half* src = W + (size_t)(ok ? r : 0) * 128 + kc + s * 8;
                uint32_t sa = sbB + (uint32_t)(buf * BN * KP + r * KP + s * 8) * 2;
                CPASYNC16(sa, src, ok ? 16 : 0);
            }
        }
        CPCOMMIT();
    };

    float acc[2][NF][4];
    #pragma unroll
    for (int mt = 0; mt < 2; mt++)
        #pragma unroll
        for (int f = 0; f < NF; f++)
            #pragma unroll
            for (int j = 0; j < 4; j++) acc[mt][f][j] = 0.f;

    const int nch = DUAL ? 4 : 2;
    load_chunk(0, 0);
    load_chunk(1, 1);

    for (int c = 0; c < nch; c++) {
        if (c + 1 < nch) { CPWAIT(1); } else { CPWAIT(0); }
        __syncthreads();
        const int buf = c & 1;
        const __half* Ab = As + buf * 128 * KP;
        const __half* Bb = Bs + buf * BN * KP;
        #pragma unroll
        for (int kk = 0; kk < 64; kk += 16) {
            uint32_t afr[2][4];
            #pragma unroll
            for (int mt = 0; mt < 2; mt++) {
                int rb = m_base + mt * 16 + g;
                afr[mt][0] = *(const uint32_t*)&Ab[(rb)     * KP + kk + 2 * tig];
                afr[mt][1] = *(const uint32_t*)&Ab[(rb + 8) * KP + kk + 2 * tig];
                afr[mt][2] = *(const uint32_t*)&Ab[(rb)     * KP + kk + 8 + 2 * tig];
                afr[mt][3] = *(const uint32_t*)&Ab[(rb + 8) * KP + kk + 8 + 2 * tig];
            }
            uint32_t bfr[NF][2];
            #pragma unroll
            for (int f = 0; f < NF; f++) {
                int nr = n_base + f * 8 + g;
                bfr[f][0] = *(const uint32_t*)&Bb[nr * KP + kk + 2 * tig];
                bfr[f][1] = *(const uint32_t*)&Bb[nr * KP + kk + 8 + 2 * tig];
            }
            #pragma unroll
            for (int mt = 0; mt < 2; mt++)
                #pragma unroll
                for (int f = 0; f < NF; f++)
                    mma_f16(acc[mt][f], afr[mt], bfr[f]);
        }
        __syncthreads();
        if (c + 2 < nch) load_chunk(c + 2, buf);
    }

    float* outf = (float*)out_v;
    __half* outh = (__half*)out_v;
    #pragma unroll
    for (int mt = 0; mt < 2; mt++) {
        int row = row0 + m_base + mt * 16 + g;
        #pragma unroll
        for (int f = 0; f < NF; f++) {
            int col = n_base + f * 8 + 2 * tig;
            if (col >= fout) continue;
            float bx = bias_s[col], by = bias_s[col + 1];
            float v0 = acc[mt][f][0] + bx, v1 = acc[mt][f][1] + by;
            float v2 = acc[mt][f][2] + bx, v3 = acc[mt][f][3] + by;
            if (do_relu) {
                v0 = fmaxf(v0, 0.f); v1 = fmaxf(v1, 0.f);
                v2 = fmaxf(v2, 0.f); v3 = fmaxf(v3, 0.f);
            }
            if (OUT_HALF) {
                if (row < n)
                    *(__half2*)(outh + (size_t)row * fout + col) = __floats2half2_rn(v0, v1);
                if (row + 8 < n)
                    *(__half2*)(outh + (size_t)(row + 8) * fout + col) = __floats2half2_rn(v2, v3);
            } else {
                if (row < n)
                    *(float2*)(outf + (size_t)row * fout + col) = make_float2(v0, v1);
                if (row + 8 < n)
                    *(float2*)(outf + (size_t)(row + 8) * fout + col) = make_float2(v2, v3);
            }
        }
    }
}

// ------------- fused combine-1 + pool-2 (all dims 128) -----------------------
__global__ void __launch_bounds__(256, 2) fused_mid_kernel(
    const __half* __restrict__ X0, const __half* __restrict__ X1,
    const __half* __restrict__ W0, const __half* __restrict__ W1,
    const __half* __restrict__ W2,
    const float* __restrict__ b0, const float* __restrict__ b1,
    const float* __restrict__ b2,
    __half* __restrict__ out_h, __half* __restrict__ out_m, int n)
{
    extern __shared__ __align__(16) __half smem_h[];
    __half* As = smem_h;                     // [2][128*KP]
    __half* Bs = smem_h + 2 * 128 * KP;      // [2][128*KP]
    float* bias_s  = (float*)(smem_h + 4 * 128 * KP);   // [128]
    float* bias2_s = bias_s + 128;                       // [128]

    const int tid   = threadIdx.x;
    const int lane  = tid & 31, wid = tid >> 5;
    const int g     = lane >> 2, tig = lane & 3;
    const int m_base = (wid & 3) * 32;
    const int n_base = (wid >> 2) * 64;
    const int row0  = blockIdx.x * 128;
    const uint32_t sbA = smem_to_u32(smem_h);
    const uint32_t sbB = sbA + 2 * 128 * KP * 2;

    if (tid < 128) {
        bias_s[tid]  = b0[tid] + b1[tid];
        bias2_s[tid] = b2[tid];
    }

    auto load_chunk = [&](int c, int buf) {
        const __half* X = (c < 2) ? X0 : X1;
        const __half* W = (c < 2) ? W0 : W1;
        const int kc = (c & 1) * 64;
        #pragma unroll
        for (int i = 0; i < 4; i++) {
            int lin = i * 256 + tid;
            int r = lin >> 3, s = lin & 7;
            int gr = row0 + r;
            int ok = (gr < n);
            const __half* src = X + (size_t)(ok ? gr : 0) * 128 + kc + s * 8;
            uint32_t sa = sbA + (uint32_t)(buf * 128 * KP + r * KP + s * 8) * 2;
            CPASYNC16(sa, src, ok ? 16 : 0);
        }
        #pragma unroll
        for (int i = 0; i < 4; i++) {
            int lin = i * 256 + tid;
            int r = lin >> 3, s = lin & 7;
            const __half* src = W + (size_t)r * 128 + kc + s * 8;
            uint32_t sa = sbB + (uint32_t)(buf * 128 * KP + r * KP + s * 8) * 2;
            CPASYNC16(sa, src, 16);
        }
        CPCOMMIT();
    };
    auto load_w2_chunk = [&](int idx) {
        const int kc = idx * 64;
        #pragma unroll
        for (int i = 0; i < 4; i++) {
            int lin = i * 256 + tid;
            int r = lin >> 3, s = lin & 7;
            const __half* src = W2 + (size_t)r * 128 + kc + s * 8;
            uint32_t sa = sbB + (uint32_t)(idx * 128 * KP + r * KP + s * 8) * 2;
            CPASYNC16(sa, src, 16);
        }
        CPCOMMIT();
    };

    float acc[2][8][4];
    auto zero_acc = [&]() {
        #pragma unroll
        for (int mt = 0; mt < 2; mt++)
            #pragma unroll
            for (int f = 0; f < 8; f++)
                #pragma unroll
                for (int j = 0; j < 4; j++) acc[mt][f][j] = 0.f;
    };
    auto compute_chunk = [&](const __half* Ab, const __half* Bb) {
        #pragma unroll
        for (int kk = 0; kk < 64; kk += 16) {
            uint32_t afr[2][4];
            #pragma unroll
            for (int mt = 0; mt < 2; mt++) {
                int rb = m_base + mt * 16 + g;
                afr[mt][0] = *(const uint32_t*)&Ab[(rb)     * KP + kk + 2 * tig];
                afr[mt][1] = *(const uint32_t*)&Ab[(rb + 8) * KP + kk + 2 * tig];
                afr[mt][2] = *(const uint32_t*)&Ab[(rb)     * KP + kk + 8 + 2 * tig];
                afr[mt][3] = *(const uint32_t*)&Ab[(rb + 8) * KP + kk + 8 + 2 * tig];
            }
            uint32_t bfr[8][2];
            #pragma unroll
            for (int f = 0; f < 8; f++) {
                int nr = n_base + f * 8 + g;
                bfr[f][0] = *(const uint32_t*)&Bb[nr * KP + kk + 2 * tig];
                bfr[f][1] = *(const uint32_t*)&Bb[nr * KP + kk + 8 + 2 * tig];
            }
            #pragma unroll
            for (int mt = 0; mt < 2; mt++)
                #pragma unroll
                for (int f = 0; f < 8; f++)
                    mma_f16(acc[mt][f], afr[mt], bfr[f]);
        }
    };

    zero_acc();
    load_chunk(0, 0);
    load_chunk(1, 1);

    #pragma unroll
    for (int c = 0; c < 4; c++) {
        CPWAIT(1);
        __syncthreads();
        const int buf = c & 1;
        compute_chunk(As + buf * 128 * KP, Bs + buf * 128 * KP);
        __syncthreads();
        if (c < 2) load_chunk(c + 2, buf);
        else       load_w2_chunk(c - 2);
    }

    #pragma unroll
    for (int mt = 0; mt < 2; mt++) {
        int lrow = m_base + mt * 16 + g;
        int row  = row0 + lrow;
        #pragma unroll
        for (int f = 0; f < 8; f++) {
            int col = n_base + f * 8 + 2 * tig;
            float bx = bias_s[col], by = bias_s[col + 1];
            float v0 = fmaxf(acc[mt][f][0] + bx, 0.f);
            float v1 = fmaxf(acc[mt][f][1] + by, 0.f);
            float v2 = fmaxf(acc[mt][f][2] + bx, 0.f);
            float v3 = fmaxf(acc[mt][f][3] + by, 0.f);
            __half2 h01 = __floats2half2_rn(v0, v1);
            __half2 h23 = __floats2half2_rn(v2, v3);
            if (row < n)
                *(__half2*)(out_h + (size_t)row * 128 + col) = h01;
            if (row + 8 < n)
                *(__half2*)(out_h + (size_t)(row + 8) * 128 + col) = h23;
            __half* dstA = As + (col >= 64 ? 1 : 0) * 128 * KP;
            int ck = col & 63;
            *(__half2*)&dstA[(lrow)     * KP + ck] = h01;
            *(__half2*)&dstA[(lrow + 8) * KP + ck] = h23;
        }
    }
    CPWAIT(0);
    __syncthreads();

    zero_acc();
    compute_chunk(As, Bs);
    compute_chunk(As + 128 * KP, Bs + 128 * KP);

    #pragma unroll
    for (int mt = 0; mt < 2; mt++) {
        int row = row0 + m_base + mt * 16 + g;
        #pragma unroll
        for (int f = 0; f < 8; f++) {
            int col = n_base + f * 8 + 2 * tig;
            float bx = bias2_s[col], by = bias2_s[col + 1];
            float v0 = fmaxf(acc[mt][f][0] + bx, 0.f);
            float v1 = fmaxf(acc[mt][f][1] + by, 0.f);
            float v2 = fmaxf(acc[mt][f][2] + bx, 0.f);
            float v3 = fmaxf(acc[mt][f][3] + by, 0.f);
            if (row < n)
                *(__half2*)(out_m + (size_t)row * 128 + col) = __floats2half2_rn(v0, v1);
            if (row + 8 < n)
                *(__half2*)(out_m + (size_t)(row + 8) * 128 + col) = __floats2half2_rn(v2, v3);
        }
    }
}

// ------------------------- prep: conv_x | conv_w (no hist) --------------------
#define CXB 12500   // conv_x blocks (NN*FDIM/4/256)
#define CWB 296     // conv_w blocks (75776/256)
__global__ void __launch_bounds__(256) prep_kernel(
    const float4* __restrict__ in_feat, __half2* __restrict__ xh,
    const float* w1, const float* w2, const float* w3,
    const float* w4, const float* w5, const float* w6,
    __half* __restrict__ wh)
{
    int b = blockIdx.x;
    if (b < CXB) {
        int i = b * 256 + threadIdx.x;
        float4 v = in_feat[i];
        xh[i * 2 + 0] = __floats2half2_rn(v.x, v.y);
        xh[i * 2 + 1] = __floats2half2_rn(v.z, v.w);
    } else {
        int i = (b - CXB) * 256 + threadIdx.x;
        const float* s; int off;
        if      (i < 16384) { s = w1; off = i; }
        else if (i < 32768) { s = w2; off = i - 16384; }
        else if (i < 49152) { s = w3; off = i - 32768; }
        else if (i < 65536) { s = w4; off = i - 49152; }
        else if (i < 70656) { s = w5; off = i - 65536; }
        else if (i < 75776) { s = w6; off = i - 70656; }
        else return;
        wh[i] = __float2half_rn(s[off]);
    }
}

__global__ void hist_kernel(const int* __restrict__ dst, int* __restrict__ deg)
{
    int e = blockIdx.x * 256 + threadIdx.x;
    if (e < NE) atomicAdd(&deg[dst[e]], 1);
}

// ------------------------- CSR scan + scatter ----------------------------------
__global__ void __launch_bounds__(1024) scanA_kernel(
    const int* __restrict__ deg, int* __restrict__ off, int* __restrict__ part)
{
    __shared__ int wsum[32];
    const int tid = threadIdx.x, lane = tid & 31, w = tid >> 5;
    int idx = blockIdx.x * 1024 + tid;
    int v = (idx < NN) ? deg[idx] : 0;
    int incl = v;
    #pragma unroll
    for (int d = 1; d < 32; d <<= 1) {
        int t = __shfl_up_sync(~0u, incl, d);
        if (lane >= d) incl += t;
    }
    if (lane == 31) wsum[w] = incl;
    __syncthreads();
    if (w == 0) {
        int s = wsum[lane], si = s;
        #pragma unroll
        for (int d = 1; d < 32; d <<= 1) {
            int t = __shfl_up_sync(~0u, si, d);
            if (lane >= d) si += t;
        }
        wsum[lane] = si - s;
    }
    __syncthreads();
    int excl = incl - v + wsum[w];
    if (idx < NN) off[idx] = excl;
    if (tid == 1023) part[blockIdx.x] = excl + v;
}

__global__ void __launch_bounds__(128) scanB_kernel(int* __restrict__ part,
                                                    int* __restrict__ off, int ntiles)
{
    __shared__ int wsum[4];
    const int tid = threadIdx.x, lane = tid & 31, w = tid >> 5;
    int v = (tid < ntiles) ? part[tid] : 0;
    int incl = v;
    #pragma unroll
    for (int d = 1; d < 32; d <<= 1) {
        int t = __shfl_up_sync(~0u, incl, d);
        if (lane >= d) incl += t;
    }
    if (lane == 31) wsum[w] = incl;
    __syncthreads();
    int woff = 0;
    #pragma unroll
    for (int i = 0; i < 4; i++) if (i < w) woff += wsum[i];
    int excl = incl - v + woff;
    if (tid < ntiles) part[tid] = excl;
    if (tid == 127) off[NN] = excl + v;
}

__global__ void scanC_kernel(int* __restrict__ off, int* __restrict__ pos,
                             const int* __restrict__ part)
{
    int idx = blockIdx.x * 256 + threadIdx.x;
    if (idx < NN) {
        int o = off[idx] + part[idx >> 10];
        off[idx] = o;
        pos[idx] = o;
    }
}

__global__ void scatter_kernel(const int* __restrict__ src, const int* __restrict__ dst,
                               int* __restrict__ pos, int* __restrict__ csr)
{
    int e = blockIdx.x * 256 + threadIdx.x;
    if (e < NE) {
        int p = atomicAdd(&pos[dst[e]], 1);
        csr[p] = src[e];
    }
}

// ------------------------- segment-max via CSR (fp16) --------------------------
__global__ void __launch_bounds__(256) agg_kernel(
    const int* __restrict__ off, const int* __restrict__ csr,
    const __half2* __restrict__ m2, __half2* __restrict__ agg2)
{
    int node = blockIdx.x * 8 + (threadIdx.x >> 5);
    if (node >= NN) return;
    int lane = threadIdx.x & 31;
    int i = off[node], e1 = off[node + 1];
    const int co = lane * 2;
    __half2 mx0 = __float2half2_rn(0.f), mx1 = mx0;
    for (; i + 4 <= e1; i += 4) {
        int s0 = __ldg(&csr[i]),     s1 = __ldg(&csr[i + 1]);
        int s2 = __ldg(&csr[i + 2]), s3 = __ldg(&csr[i + 3]);
        uint2 a = *(const uint2*)(m2 + (size_t)s0 * 64 + co);
        uint2 b = *(const uint2*)(m2 + (size_t)s1 * 64 + co);
        uint2 c = *(const uint2*)(m2 + (size_t)s2 * 64 + co);
        uint2 d = *(const uint2*)(m2 + (size_t)s3 * 64 + co);
        __half2 a0 = *(__half2*)&a.x, a1 = *(__half2*)&a.y;
        __half2 b0 = *(__half2*)&b.x, b1 = *(__half2*)&b.y;
        __half2 c0 = *(__half2*)&c.x, c1 = *(__half2*)&c.y;
        __half2 d0 = *(__half2*)&d.x, d1 = *(__half2*)&d.y;
        mx0 = __hmax2(mx0, __hmax2(__hmax2(a0, b0), __hmax2(c0, d0)));
        mx1 = __hmax2(mx1, __hmax2(__hmax2(a1, b1), __hmax2(c1, d1)));
    }
    for (; i < e1; i++) {
        int s = __ldg(&csr[i]);
        uint2 a = *(const uint2*)(m2 + (size_t)s * 64 + co);
        mx0 = __hmax2(mx0, *(__half2*)&a.x);
        mx1 = __hmax2(mx1, *(__half2*)&a.y);
    }
    agg2[(size_t)node * 64 + co]     = mx0;
    agg2[(size_t)node * 64 + co + 1] = mx1;
}

// ===============================================================================
extern "C" void kernel_launch(void* const* d_in, const int* in_sizes, int n_in,
                              void* d_out, int out_size)
{
    const float* in_feat  = (const float*)d_in[0];
    const int*   src      = (const int*)  d_in[1];
    const int*   dst      = (const int*)  d_in[2];
    const float* pool_w1  = (const float*)d_in[3];
    const float* pool_b1  = (const float*)d_in[4];
    const float* self_w1  = (const float*)d_in[5];
    const float* self_b1  = (const float*)d_in[6];
    const float* neigh_w1 = (const float*)d_in[7];
    const float* neigh_b1 = (const float*)d_in[8];
    const float* pool_w2  = (const float*)d_in[9];
    const float* pool_b2  = (const float*)d_in[10];
    const float* self_w2  = (const float*)d_in[11];
    const float* self_b2  = (const float*)d_in[12];
    const float* neigh_w2 = (const float*)d_in[13];
    const float* neigh_b2 = (const float*)d_in[14];

    __half *mh, *aggh, *hh, *xh, *wh;
    int *deg, *off, *pos, *csr, *part;
    cudaGetSymbolAddress((void**)&mh,   g_mh);
    cudaGetSymbolAddress((void**)&aggh, g_aggh);
    cudaGetSymbolAddress((void**)&hh,   g_hh);
    cudaGetSymbolAddress((void**)&xh,   g_xh);
    cudaGetSymbolAddress((void**)&wh,   g_wh);
    cudaGetSymbolAddress((void**)&deg,  g_deg);
    cudaGetSymbolAddress((void**)&off,  g_off);
    cudaGetSymbolAddress((void**)&pos,  g_pos);
    cudaGetSymbolAddress((void**)&csr,  g_csr);
    cudaGetSymbolAddress((void**)&part, g_part);

    const int ggrid  = (NN + 127) / 128;     // 782
    const int ngrid  = (NN + 7) / 8;
    const int ntiles = (NN + 1023) / 1024;   // 98
    const int SMEM_128  = (2 * 128 * KP + 2 * 128 * KP) * 2 + 128 * 4;   // 74240 B
    const int SMEM_48   = (2 * 128 * KP + 2 * 48 * KP) * 2 + 48 * 4;     // 50880 B
    const int SMEM_FUSE = 4 * 128 * KP * 2 + 256 * 4;                    // 74752 B

    cudaFuncSetAttribute(mma_gemm_kernel<128, false, true>,
                         cudaFuncAttributeMaxDynamicSharedMemorySize, SMEM_128);
    cudaFuncSetAttribute(mma_gemm_kernel<48, true, false>,
                         cudaFuncAttributeMaxDynamicSharedMemorySize, SMEM_48);
    cudaFuncSetAttribute(fused_mid_kernel,
                         cudaFuncAttributeMaxDynamicSharedMemorySize, SMEM_FUSE);

    // ---- fork: CSR build on side stream, prep+pool-1 on main stream ----
    cudaStream_t s2;
    cudaEvent_t evF, evJ;
    cudaStreamCreateWithFlags(&s2, cudaStreamNonBlocking);
    cudaEventCreateWithFlags(&evF, cudaEventDisableTiming);
    cudaEventCreateWithFlags(&evJ, cudaEventDisableTiming);

    cudaEventRecord(evF, 0);
    cudaStreamWaitEvent(s2, evF, 0);

    // side stream: CSR chain
    cudaMemsetAsync(deg, 0, NN * sizeof(int), s2);
    hist_kernel<<<(NE + 255) / 256, 256, 0, s2>>>(dst, deg);
    scanA_kernel<<<ntiles, 1024, 0, s2>>>(deg, off, part);
    scanB_kernel<<<1, 128, 0, s2>>>(part, off, ntiles);
    scanC_kernel<<<(NN + 255) / 256, 256, 0, s2>>>(off, pos, part);
    scatter_kernel<<<(NE + 255) / 256, 256, 0, s2>>>(src, dst, pos, csr);
    cudaEventRecord(evJ, s2);

    // main stream: prep + pool-1 GEMM (independent of CSR)
    prep_kernel<<<CXB + CWB, 256>>>((const float4*)in_feat, (__half2*)xh,
                                    pool_w1, self_w1, neigh_w1,
                                    pool_w2, self_w2, neigh_w2, wh);
    mma_gemm_kernel<128, false, true><<<ggrid, 256, SMEM_128>>>(
        xh, nullptr, wh + WR_PW1, nullptr, pool_b1, nullptr, mh, NN, FDIM, 1);

    // join: agg needs both csr (s2) and mh (main)
    cudaStreamWaitEvent(0, evJ, 0);
    agg_kernel<<<ngrid, 256>>>(off, csr, (const __half2*)mh, (__half2*)aggh);

    // fused combine-1 + pool-2
    fused_mid_kernel<<<ggrid, 256, SMEM_FUSE>>>(
        xh, aggh, wh + WR_SW1, wh + WR_NW1, wh + WR_PW2,
        self_b1, neigh_b1, pool_b2, hh, mh, NN);
    agg_kernel<<<ngrid, 256>>>(off, csr, (const __half2*)mh, (__half2*)aggh);

    // layer-2 combine (BN=48 covers fout=40)
    mma_gemm_kernel<48, true, false><<<ggrid, 256, SMEM_48>>>(
        hh, aggh, wh + WR_SW2, wh + WR_NW2, self_b2, neigh_b2, (float*)d_out, NN, NCLS, 0);
}

// round 11
// speedup vs baseline: 1.3319x; 1.3319x over previous
#include <cuda_runtime.h>
#include <cuda_fp16.h>
#include <cstdint>

#define NN 100000
#define NE 1600000
#define FDIM 128
#define NCLS 40

// ------------------------- device scratch (no allocs) -----------------------
__device__ __align__(16) __half g_mh[(size_t)NN * FDIM];   // pool messages (fp16)
__device__ __align__(16) __half g_aggh[(size_t)NN * FDIM]; // segment-max agg (fp16)
__device__ __align__(16) __half g_hh[(size_t)NN * FDIM];   // layer-1 hidden (fp16)
__device__ __align__(16) __half g_xh[(size_t)NN * FDIM];   // fp16 in_feat
__device__ __align__(16) __half g_wh[75776];               // fp16 weights (6 matrices)
__device__ int   g_deg[NN];
__device__ int   g_off[NN + 1];
__device__ int   g_pos[NN];
__device__ int   g_csr[NE];
__device__ int   g_part[128];               // scan tile partials

// weight offsets inside g_wh
#define WR_PW1 0
#define WR_SW1 16384
#define WR_NW1 32768
#define WR_PW2 49152
#define WR_SW2 65536
#define WR_NW2 70656

// ------------------------- PTX helpers --------------------------------------
__device__ __forceinline__ uint32_t smem_to_u32(const void* p) {
    uint32_t a;
    asm("{ .reg .u64 t; cvta.to.shared.u64 t, %1; cvt.u32.u64 %0, t; }"
        : "=r"(a) : "l"(p));
    return a;
}
#define CPASYNC16(sa, ga, sz) \
    asm volatile("cp.async.cg.shared.global [%0], [%1], 16, %2;" \
                 :: "r"(sa), "l"(ga), "r"(sz))
#define CPCOMMIT() asm volatile("cp.async.commit_group;" ::: "memory")
#define CPWAIT(N)  asm volatile("cp.async.wait_group %0;" :: "n"(N) : "memory")

// m16n8k16 fp16 HMMA, f32 accum. Base PTX (sm_80+): compiles at compute_103.
__device__ __forceinline__ void mma_f16(float* d, const uint32_t* a, const uint32_t* b)
{
    asm volatile(
        "mma.sync.aligned.m16n8k16.row.col.f32.f16.f16.f32 "
        "{%0,%1,%2,%3}, {%4,%5,%6,%7}, {%8,%9}, {%0,%1,%2,%3};"
        : "+f"(d[0]), "+f"(d[1]), "+f"(d[2]), "+f"(d[3])
        : "r"(a[0]), "r"(a[1]), "r"(a[2]), "r"(a[3]),
          "r"(b[0]), "r"(b[1]));
}

#define KP 72   // padded smem k stride (halves)

// ------------------------- fp16 warp-MMA GEMM (generic) ----------------------
template<int BN, bool DUAL, bool OUT_HALF>
__global__ void __launch_bounds__(256, 2) mma_gemm_kernel(
    const __half* __restrict__ X0, const __half* __restrict__ X1,
    const __half* __restrict__ W0, const __half* __restrict__ W1,
    const float* __restrict__ b0, const float* __restrict__ b1,
    void* __restrict__ out_v, int n, int fout, int do_relu)
{
    constexpr int NF = BN / 16;
    extern __shared__ __align__(16) __half smem_h[];
    __half* As = smem_h;                     // [2][128*KP]
    __half* Bs = smem_h + 2 * 128 * KP;      // [2][BN*KP]
    float* bias_s = (float*)(smem_h + 2 * 128 * KP + 2 * BN * KP);

    const int tid   = threadIdx.x;
    const int lane  = tid & 31, wid = tid >> 5;
    const int g     = lane >> 2, tig = lane & 3;
    const int m_base = (wid & 3) * 32;
    const int n_base = (wid >> 2) * (BN / 2);
    const int row0  = blockIdx.x * 128;
    const uint32_t sbA = smem_to_u32(smem_h);
    const uint32_t sbB = sbA + 2 * 128 * KP * 2;

    if (tid < BN) {
        float bv = 0.f;
        if (tid < fout) { bv = b0[tid]; if (b1 != nullptr) bv += b1[tid]; }
        bias_s[tid] = bv;
    }

    auto load_chunk = [&](int c, int buf) {
        const __half* X = (c < 2) ? X0 : X1;
        const __half* W = (c < 2) ? W0 : W1;
        const int kc = (c & 1) * 64;
        #pragma unroll
        for (int i = 0; i < 4; i++) {
            int lin = i * 256 + tid;
            int r = lin >> 3, s = lin & 7;
            int gr = row0 + r;
            int ok = (gr < n);
            const __half* src = X + (size_t)(ok ? gr : 0) * 128 + kc + s * 8;
            uint32_t sa = sbA + (uint32_t)(buf * 128 * KP + r * KP + s * 8) * 2;
            CPASYNC16(sa, src, ok ? 16 : 0);
        }
        #pragma unroll
        for (int i = 0; i < (BN * 8 + 255) / 256; i++) {
            int lin = i * 256 + tid;
            if (lin < BN * 8) {
                int r = lin >> 3, s = lin & 7;
                int ok = (r < fout);
                const __half* src = W + (size_t)(ok ? r : 0) * 128 + kc + s * 8;
                uint32_t sa = sbB + (uint32_t)(buf * BN * KP + r * KP + s * 8) * 2;
                CPASYNC16(sa, src, ok ? 16 : 0);
            }
        }
        CPCOMMIT();
    };

    float acc[2][NF][4];
    #pragma unroll
    for (int mt = 0; mt < 2; mt++)
        #pragma unroll
        for (int f = 0; f < NF; f++)
            #pragma unroll
            for (int j = 0; j < 4; j++) acc[mt][f][j] = 0.f;

    const int nch = DUAL ? 4 : 2;
    load_chunk(0, 0);
    load_chunk(1, 1);

    for (int c = 0; c < nch; c++) {
        if (c + 1 < nch) { CPWAIT(1); } else { CPWAIT(0); }
        __syncthreads();
        const int buf = c & 1;
        const __half* Ab = As + buf * 128 * KP;
        const __half* Bb = Bs + buf * BN * KP;
        #pragma unroll
        for (int kk = 0; kk < 64; kk += 16) {
            uint32_t afr[2][4];
            #pragma unroll
            for (int mt = 0; mt < 2; mt++) {
                int rb = m_base + mt * 16 + g;
                afr[mt][0] = *(const uint32_t*)&Ab[(rb)     * KP + kk + 2 * tig];
                afr[mt][1] = *(const uint32_t*)&Ab[(rb + 8) * KP + kk + 2 * tig];
                afr[mt][2] = *(const uint32_t*)&Ab[(rb)     * KP + kk + 8 + 2 * tig];
                afr[mt][3] = *(const uint32_t*)&Ab[(rb + 8) * KP + kk + 8 + 2 * tig];
            }
            uint32_t bfr[NF][2];
            #pragma unroll
            for (int f = 0; f < NF; f++) {
                int nr = n_base + f * 8 + g;
                bfr[f][0] = *(const uint32_t*)&Bb[nr * KP + kk + 2 * tig];
                bfr[f][1] = *(const uint32_t*)&Bb[nr * KP + kk + 8 + 2 * tig];
            }
            #pragma unroll
            for (int mt = 0; mt < 2; mt++)
                #pragma unroll
                for (int f = 0; f < NF; f++)
                    mma_f16(acc[mt][f], afr[mt], bfr[f]);
        }
        __syncthreads();
        if (c + 2 < nch) load_chunk(c + 2, buf);
    }

    float* outf = (float*)out_v;
    __half* outh = (__half*)out_v;
    #pragma unroll
    for (int mt = 0; mt < 2; mt++) {
        int row = row0 + m_base + mt * 16 + g;
        #pragma unroll
        for (int f = 0; f < NF; f++) {
            int col = n_base + f * 8 + 2 * tig;
            if (col >= fout) continue;
            float bx = bias_s[col], by = bias_s[col + 1];
            float v0 = acc[mt][f][0] + bx, v1 = acc[mt][f][1] + by;
            float v2 = acc[mt][f][2] + bx, v3 = acc[mt][f][3] + by;
            if (do_relu) {
                v0 = fmaxf(v0, 0.f); v1 = fmaxf(v1, 0.f);
                v2 = fmaxf(v2, 0.f); v3 = fmaxf(v3, 0.f);
            }
            if (OUT_HALF) {
                if (row < n)
                    *(__half2*)(outh + (size_t)row * fout + col) = __floats2half2_rn(v0, v1);
                if (row + 8 < n)
                    *(__half2*)(outh + (size_t)(row + 8) * fout + col) = __floats2half2_rn(v2, v3);
            } else {
                if (row < n)
                    *(float2*)(outf + (size_t)row * fout + col) = make_float2(v0, v1);
                if (row + 8 < n)
                    *(float2*)(outf + (size_t)(row + 8) * fout + col) = make_float2(v2, v3);
            }
        }
    }
}

// ------------- fused combine-1 + pool-2 (all dims 128) -----------------------
__global__ void __launch_bounds__(256, 2) fused_mid_kernel(
    const __half* __restrict__ X0, const __half* __restrict__ X1,
    const __half* __restrict__ W0, const __half* __restrict__ W1,
    const __half* __restrict__ W2,
    const float* __restrict__ b0, const float* __restrict__ b1,
    const float* __restrict__ b2,
    __half* __restrict__ out_h, __half* __restrict__ out_m, int n)
{
    extern __shared__ __align__(16) __half smem_h[];
    __half* As = smem_h;                     // [2][128*KP]
    __half* Bs = smem_h + 2 * 128 * KP;      // [2][128*KP]
    float* bias_s  = (float*)(smem_h + 4 * 128 * KP);   // [128]
    float* bias2_s = bias_s + 128;                       // [128]

    const int tid   = threadIdx.x;
    const int lane  = tid & 31, wid = tid >> 5;
    const int g     = lane >> 2, tig = lane & 3;
    const int m_base = (wid & 3) * 32;
    const int n_base = (wid >> 2) * 64;
    const int row0  = blockIdx.x * 128;
    const uint32_t sbA = smem_to_u32(smem_h);
    const uint32_t sbB = sbA + 2 * 128 * KP * 2;

    if (tid < 128) {
        bias_s[tid]  = b0[tid] + b1[tid];
        bias2_s[tid] = b2[tid];
    }

    auto load_chunk = [&](int c, int buf) {
        const __half* X = (c < 2) ? X0 : X1;
        const __half* W = (c < 2) ? W0 : W1;
        const int kc = (c & 1) * 64;
        #pragma unroll
        for (int i = 0; i < 4; i++) {
            int lin = i * 256 + tid;
            int r = lin >> 3, s = lin & 7;
            int gr = row0 + r;
            int ok = (gr < n);
            const __half* src = X + (size_t)(ok ? gr : 0) * 128 + kc + s * 8;
            uint32_t sa = sbA + (uint32_t)(buf * 128 * KP + r * KP + s * 8) * 2;
            CPASYNC16(sa, src, ok ? 16 : 0);
        }
        #pragma unroll
        for (int i = 0; i < 4; i++) {
            int lin = i * 256 + tid;
            int r = lin >> 3, s = lin & 7;
            const __half* src = W + (size_t)r * 128 + kc + s * 8;
            uint32_t sa = sbB + (uint32_t)(buf * 128 * KP + r * KP + s * 8) * 2;
            CPASYNC16(sa, src, 16);
        }
        CPCOMMIT();
    };
    auto load_w2_chunk = [&](int idx) {
        const int kc = idx * 64;
        #pragma unroll
        for (int i = 0; i < 4; i++) {
            int lin = i * 256 + tid;
            int r = lin >> 3, s = lin & 7;
            const __half* src = W2 + (size_t)r * 128 + kc + s * 8;
            uint32_t sa = sbB + (uint32_t)(idx * 128 * KP + r * KP + s * 8) * 2;
            CPASYNC16(sa, src, 16);
        }
        CPCOMMIT();
    };

    float acc[2][8][4];
    auto zero_acc = [&]() {
        #pragma unroll
        for (int mt = 0; mt < 2; mt++)
            #pragma unroll
            for (int f = 0; f < 8; f++)
                #pragma unroll
                for (int j = 0; j < 4; j++) acc[mt][f][j] = 0.f;
    };
    auto compute_chunk = [&](const __half* Ab, const __half* Bb) {
        #pragma unroll
        for (int kk = 0; kk < 64; kk += 16) {
            uint32_t afr[2][4];
            #pragma unroll
            for (int mt = 0; mt < 2; mt++) {
                int rb = m_base + mt * 16 + g;
                afr[mt][0] = *(const uint32_t*)&Ab[(rb)     * KP + kk + 2 * tig];
                afr[mt][1] = *(const uint32_t*)&Ab[(rb + 8) * KP + kk + 2 * tig];
                afr[mt][2] = *(const uint32_t*)&Ab[(rb)     * KP + kk + 8 + 2 * tig];
                afr[mt][3] = *(const uint32_t*)&Ab[(rb + 8) * KP + kk + 8 + 2 * tig];
            }
            uint32_t bfr[8][2];
            #pragma unroll
            for (int f = 0; f < 8; f++) {
                int nr = n_base + f * 8 + g;
                bfr[f][0] = *(const uint32_t*)&Bb[nr * KP + kk + 2 * tig];
                bfr[f][1] = *(const uint32_t*)&Bb[nr * KP + kk + 8 + 2 * tig];
            }
            #pragma unroll
            for (int mt = 0; mt < 2; mt++)
                #pragma unroll
                for (int f = 0; f < 8; f++)
                    mma_f16(acc[mt][f], afr[mt], bfr[f]);
        }
    };

    zero_acc();
    load_chunk(0, 0);
    load_chunk(1, 1);

    #pragma unroll
    for (int c = 0; c < 4; c++) {
        CPWAIT(1);
        __syncthreads();
        const int buf = c & 1;
        compute_chunk(As + buf * 128 * KP, Bs + buf * 128 * KP);
        __syncthreads();
        if (c < 2) load_chunk(c + 2, buf);
        else       load_w2_chunk(c - 2);
    }

    #pragma unroll
    for (int mt = 0; mt < 2; mt++) {
        int lrow = m_base + mt * 16 + g;
        int row  = row0 + lrow;
        #pragma unroll
        for (int f = 0; f < 8; f++) {
            int col = n_base + f * 8 + 2 * tig;
            float bx = bias_s[col], by = bias_s[col + 1];
            float v0 = fmaxf(acc[mt][f][0] + bx, 0.f);
            float v1 = fmaxf(acc[mt][f][1] + by, 0.f);
            float v2 = fmaxf(acc[mt][f][2] + bx, 0.f);
            float v3 = fmaxf(acc[mt][f][3] + by, 0.f);
            __half2 h01 = __floats2half2_rn(v0, v1);
            __half2 h23 = __floats2half2_rn(v2, v3);
            if (row < n)
                *(__half2*)(out_h + (size_t)row * 128 + col) = h01;
            if (row + 8 < n)
                *(__half2*)(out_h + (size_t)(row + 8) * 128 + col) = h23;
            __half* dstA = As + (col >= 64 ? 1 : 0) * 128 * KP;
            int ck = col & 63;
            *(__half2*)&dstA[(lrow)     * KP + ck] = h01;
            *(__half2*)&dstA[(lrow + 8) * KP + ck] = h23;
        }
    }
    CPWAIT(0);
    __syncthreads();

    zero_acc();
    compute_chunk(As, Bs);
    compute_chunk(As + 128 * KP, Bs + 128 * KP);

    #pragma unroll
    for (int mt = 0; mt < 2; mt++) {
        int row = row0 + m_base + mt * 16 + g;
        #pragma unroll
        for (int f = 0; f < 8; f++) {
            int col = n_base + f * 8 + 2 * tig;
            float bx = bias2_s[col], by = bias2_s[col + 1];
            float v0 = fmaxf(acc[mt][f][0] + bx, 0.f);
            float v1 = fmaxf(acc[mt][f][1] + by, 0.f);
            float v2 = fmaxf(acc[mt][f][2] + bx, 0.f);
            float v3 = fmaxf(acc[mt][f][3] + by, 0.f);
            if (row < n)
                *(__half2*)(out_m + (size_t)row * 128 + col) = __floats2half2_rn(v0, v1);
            if (row + 8 < n)
                *(__half2*)(out_m + (size_t)(row + 8) * 128 + col) = __floats2half2_rn(v2, v3);
        }
    }
}

// ------------------------- fused prep: conv_x | conv_w | hist ------------------
#define CXB 12500   // conv_x blocks (NN*FDIM/4/256)
#define CWB 296     // conv_w blocks (75776/256)
#define HB  6250    // hist blocks (NE/256)
__global__ void __launch_bounds__(256) prep_kernel(
    const float4* __restrict__ in_feat, __half2* __restrict__ xh,
    const float* w1, const float* w2, const float* w3,
    const float* w4, const float* w5, const float* w6,
    __half* __restrict__ wh,
    const int* __restrict__ dst, int* __restrict__ deg)
{
    int b = blockIdx.x;
    if (b < CXB) {
        int i = b * 256 + threadIdx.x;
        float4 v = in_feat[i];
        xh[i * 2 + 0] = __floats2half2_rn(v.x, v.y);
        xh[i * 2 + 1] = __floats2half2_rn(v.z, v.w);
    } else if (b < CXB + CWB) {
        int i = (b - CXB) * 256 + threadIdx.x;
        const float* s; int off;
        if      (i < 16384) { s = w1; off = i; }
        else if (i < 32768) { s = w2; off = i - 16384; }
        else if (i < 49152) { s = w3; off = i - 32768; }
        else if (i < 65536) { s = w4; off = i - 49152; }
        else if (i < 70656) { s = w5; off = i - 65536; }
        else if (i < 75776) { s = w6; off = i - 70656; }
        else return;
        wh[i] = __float2half_rn(s[off]);
    } else {
        int e = (b - CXB - CWB) * 256 + threadIdx.x;
        if (e < NE) atomicAdd(&deg[dst[e]], 1);
    }
}

// ------------------------- CSR scan + scatter ----------------------------------
__global__ void __launch_bounds__(1024) scanA_kernel(
    const int* __restrict__ deg, int* __restrict__ off, int* __restrict__ part)
{
    __shared__ int wsum[32];
    const int tid = threadIdx.x, lane = tid & 31, w = tid >> 5;
    int idx = blockIdx.x * 1024 + tid;
    int v = (idx < NN) ? deg[idx] : 0;
    int incl = v;
    #pragma unroll
    for (int d = 1; d < 32; d <<= 1) {
        int t = __shfl_up_sync(~0u, incl, d);
        if (lane >= d) incl += t;
    }
    if (lane == 31) wsum[w] = incl;
    __syncthreads();
    if (w == 0) {
        int s = wsum[lane], si = s;
        #pragma unroll
        for (int d = 1; d < 32; d <<= 1) {
            int t = __shfl_up_sync(~0u, si, d);
            if (lane >= d) si += t;
        }
        wsum[lane] = si - s;
    }
    __syncthreads();
    int excl = incl - v + wsum[w];
    if (idx < NN) off[idx] = excl;
    if (tid == 1023) part[blockIdx.x] = excl + v;
}

__global__ void __launch_bounds__(128) scanB_kernel(int* __restrict__ part,
                                                    int* __restrict__ off, int ntiles)
{
    __shared__ int wsum[4];
    const int tid = threadIdx.x, lane = tid & 31, w = tid >> 5;
    int v = (tid < ntiles) ? part[tid] : 0;
    int incl = v;
    #pragma unroll
    for (int d = 1; d < 32; d <<= 1) {
        int t = __shfl_up_sync(~0u, incl, d);
        if (lane >= d) incl += t;
    }
    if (lane == 31) wsum[w] = incl;
    __syncthreads();
    int woff = 0;
    #pragma unroll
    for (int i = 0; i < 4; i++) if (i < w) woff += wsum[i];
    int excl = incl - v + woff;
    if (tid < ntiles) part[tid] = excl;
    if (tid == 127) off[NN] = excl + v;
}

__global__ void scanC_kernel(int* __restrict__ off, int* __restrict__ pos,
                             const int* __restrict__ part)
{
    int idx = blockIdx.x * 256 + threadIdx.x;
    if (idx < NN) {
        int o = off[idx] + part[idx >> 10];
        off[idx] = o;
        pos[idx] = o;
    }
}

__global__ void scatter_kernel(const int* __restrict__ src, const int* __restrict__ dst,
                               int* __restrict__ pos, int* __restrict__ csr)
{
    int e = blockIdx.x * 256 + threadIdx.x;
    if (e < NE) {
        int p = atomicAdd(&pos[dst[e]], 1);
        csr[p] = src[e];
    }
}

// ------------------------- segment-max via CSR (fp16, LDG.64) ------------------
__global__ void __launch_bounds__(256) agg_kernel(
    const int* __restrict__ off, const int* __restrict__ csr,
    const __half2* __restrict__ m2, __half2* __restrict__ agg2)
{
    int node = blockIdx.x * 8 + (threadIdx.x >> 5);
    if (node >= NN) return;
    int lane = threadIdx.x & 31;
    int i = off[node], e1 = off[node + 1];
    const int co = lane * 2;
    __half2 mx0 = __float2half2_rn(0.f), mx1 = mx0;
    for (; i + 4 <= e1; i += 4) {
        int s0 = __ldg(&csr[i]),     s1 = __ldg(&csr[i + 1]);
        int s2 = __ldg(&csr[i + 2]), s3 = __ldg(&csr[i + 3]);
        uint2 a = *(const uint2*)(m2 + (size_t)s0 * 64 + co);
        uint2 b = *(const uint2*)(m2 + (size_t)s1 * 64 + co);
        uint2 c = *(const uint2*)(m2 + (size_t)s2 * 64 + co);
        uint2 d = *(const uint2*)(m2 + (size_t)s3 * 64 + co);
        __half2 a0 = *(__half2*)&a.x, a1 = *(__half2*)&a.y;
        __half2 b0 = *(__half2*)&b.x, b1 = *(__half2*)&b.y;
        __half2 c0 = *(__half2*)&c.x, c1 = *(__half2*)&c.y;
        __half2 d0 = *(__half2*)&d.x, d1 = *(__half2*)&d.y;
        mx0 = __hmax2(mx0, __hmax2(__hmax2(a0, b0), __hmax2(c0, d0)));
        mx1 = __hmax2(mx1, __hmax2(__hmax2(a1, b1), __hmax2(c1, d1)));
    }
    for (; i < e1; i++) {
        int s = __ldg(&csr[i]);
        uint2 a = *(const uint2*)(m2 + (size_t)s * 64 + co);
        mx0 = __hmax2(mx0, *(__half2*)&a.x);
        mx1 = __hmax2(mx1, *(__half2*)&a.y);
    }
    agg2[(size_t)node * 64 + co]     = mx0;
    agg2[(size_t)node * 64 + co + 1] = mx1;
}

// ===============================================================================
extern "C" void kernel_launch(void* const* d_in, const int* in_sizes, int n_in,
                              void* d_out, int out_size)
{
    const float* in_feat  = (const float*)d_in[0];
    const int*   src      = (const int*)  d_in[1];
    const int*   dst      = (const int*)  d_in[2];
    const float* pool_w1  = (const float*)d_in[3];
    const float* pool_b1  = (const float*)d_in[4];
    const float* self_w1  = (const float*)d_in[5];
    const float* self_b1  = (const float*)d_in[6];
    const float* neigh_w1 = (const float*)d_in[7];
    const float* neigh_b1 = (const float*)d_in[8];
    const float* pool_w2  = (const float*)d_in[9];
    const float* pool_b2  = (const float*)d_in[10];
    const float* self_w2  = (const float*)d_in[11];
    const float* self_b2  = (const float*)d_in[12];
    const float* neigh_w2 = (const float*)d_in[13];
    const float* neigh_b2 = (const float*)d_in[14];

    __half *mh, *aggh, *hh, *xh, *wh;
    int *deg, *off, *pos, *csr, *part;
    cudaGetSymbolAddress((void**)&mh,   g_mh);
    cudaGetSymbolAddress((void**)&aggh, g_aggh);
    cudaGetSymbolAddress((void**)&hh,   g_hh);
    cudaGetSymbolAddress((void**)&xh,   g_xh);
    cudaGetSymbolAddress((void**)&wh,   g_wh);
    cudaGetSymbolAddress((void**)&deg,  g_deg);
    cudaGetSymbolAddress((void**)&off,  g_off);
    cudaGetSymbolAddress((void**)&pos,  g_pos);
    cudaGetSymbolAddress((void**)&csr,  g_csr);
    cudaGetSymbolAddress((void**)&part, g_part);

    const int ggrid  = (NN + 127) / 128;     // 782
    const int ngrid  = (NN + 7) / 8;
    const int ntiles = (NN + 1023) / 1024;   // 98
    const int SMEM_128  = (2 * 128 * KP + 2 * 128 * KP) * 2 + 128 * 4;   // 74240 B
    const int SMEM_48   = (2 * 128 * KP + 2 * 48 * KP) * 2 + 48 * 4;     // 50880 B
    const int SMEM_FUSE = 4 * 128 * KP * 2 + 256 * 4;                    // 74752 B

    cudaFuncSetAttribute(mma_gemm_kernel<128, false, true>,
                         cudaFuncAttributeMaxDynamicSharedMemorySize, SMEM_128);
    cudaFuncSetAttribute(mma_gemm_kernel<48, true, false>,
                         cudaFuncAttributeMaxDynamicSharedMemorySize, SMEM_48);
    cudaFuncSetAttribute(fused_mid_kernel,
                         cudaFuncAttributeMaxDynamicSharedMemorySize, SMEM_FUSE);

    // ---- prep (fused conv_x|conv_w|hist) + CSR, single stream ----
    cudaMemsetAsync(deg, 0, NN * sizeof(int));
    prep_kernel<<<CXB + CWB + HB, 256>>>((const float4*)in_feat, (__half2*)xh,
                                         pool_w1, self_w1, neigh_w1,
                                         pool_w2, self_w2, neigh_w2, wh, dst, deg);
    scanA_kernel<<<ntiles, 1024>>>(deg, off, part);
    scanB_kernel<<<1, 128>>>(part, off, ntiles);
    scanC_kernel<<<(NN + 255) / 256, 256>>>(off, pos, part);
    scatter_kernel<<<(NE + 255) / 256, 256>>>(src, dst, pos, csr);

    // ---- layer 1 pool ----
    mma_gemm_kernel<128, false, true><<<ggrid, 256, SMEM_128>>>(
        xh, nullptr, wh + WR_PW1, nullptr, pool_b1, nullptr, mh, NN, FDIM, 1);
    agg_kernel<<<ngrid, 256>>>(off, csr, (const __half2*)mh, (__half2*)aggh);

    // ---- fused: combine-1 + pool-2 ----
    fused_mid_kernel<<<ggrid, 256, SMEM_FUSE>>>(
        xh, aggh, wh + WR_SW1, wh + WR_NW1, wh + WR_PW2,
        self_b1, neigh_b1, pool_b2, hh, mh, NN);
    agg_kernel<<<ngrid, 256>>>(off, csr, (const __half2*)mh, (__half2*)aggh);

    // ---- layer-2 combine (BN=48 covers fout=40) ----
    mma_gemm_kernel<48, true, false><<<ggrid, 256, SMEM_48>>>(
        hh, aggh, wh + WR_SW2, wh + WR_NW2, self_b2, neigh_b2, (float*)d_out, NN, NCLS, 0);
}